// round 7
// baseline (speedup 1.0000x reference)
#include <cuda_runtime.h>
#include <cuda_bf16.h>

#define BATCH 8
#define CHAN 128

__device__ float g_y64[BATCH * CHAN * 4096];   // 16 MB
__device__ float g_h64[BATCH * CHAN * 4096];   // 16 MB
__device__ float g_a32[BATCH * CHAN * 1024];   // 4 MB
__device__ float g_b32[BATCH * CHAN * 1024];   // 4 MB
__device__ float g_pool[BATCH * CHAN];

// ---------------------------------------------------------------------------
// 64x64 grid_sample * box mask, 4 batches per block (dynamic smem 64KB).
// ---------------------------------------------------------------------------
template <bool FUSE3>
__global__ void __launch_bounds__(256) sample64_kernel(
    const float* __restrict__ in, const float* __restrict__ lin,
    float* __restrict__ out,
    const float* __restrict__ geo, const float* __restrict__ box) {
    constexpr int H = 64, W = 64, HW = 4096;
    extern __shared__ float sp[];              // 4 * HW
    const int c  = blockIdx.x >> 1;
    const int b0 = (blockIdx.x & 1) * 4;

    if (FUSE3) {
        const float l0 = lin[c * 3 + 0], l1 = lin[c * 3 + 1], l2 = lin[c * 3 + 2];
        for (int j = threadIdx.x; j < 4 * HW; j += 256) {
            int pl = j >> 12, p = j & 4095;
            const float* xb = in + (size_t)(b0 + pl) * 3 * HW + p;
            sp[j] = fmaf(l0, xb[0], fmaf(l1, xb[HW], l2 * xb[2 * HW]));
        }
    } else {
        for (int j = threadIdx.x; j < 4 * HW; j += 256) {
            int pl = j >> 12, p = j & 4095;
            sp[j] = in[((size_t)(b0 + pl) * 128 + c) * HW + p];
        }
    }

    const float g0 = geo[c * 6 + 0], g1 = geo[c * 6 + 1], g2 = geo[c * 6 + 2];
    const float g3 = geo[c * 6 + 3], g4 = geo[c * 6 + 4], g5 = geo[c * 6 + 5];
    const float q0 = box[c * 6 + 0], q1 = box[c * 6 + 1], q2 = box[c * 6 + 2];
    const float q3 = box[c * 6 + 3], q4 = box[c * 6 + 4], q5 = box[c * 6 + 5];
    __syncthreads();

    float* d0 = out + ((size_t)b0 * 128 + c) * HW;

    for (int i = threadIdx.x; i < HW; i += 256) {
        int h = i >> 6, w = i & 63;
        float xs = (2.f * w + 1.f) * (1.f / W) - 1.f;
        float ys = (2.f * h + 1.f) * (1.f / H) - 1.f;

        float ix = ((fmaf(g0, xs, fmaf(g1, ys, g2)) + 1.f) * W - 1.f) * 0.5f;
        float iy = ((fmaf(g3, xs, fmaf(g4, ys, g5)) + 1.f) * H - 1.f) * 0.5f;
        float fx = floorf(ix), fy = floorf(iy);
        float wx = ix - fx, wy = iy - fy;
        int x0 = (int)fx, y0 = (int)fy;
        float vx0 = (x0 >= 0 && x0 < W) ? 1.f : 0.f;
        float vx1 = (x0 + 1 >= 0 && x0 + 1 < W) ? 1.f : 0.f;
        float vy0 = (y0 >= 0 && y0 < H) ? 1.f : 0.f;
        float vy1 = (y0 + 1 >= 0 && y0 + 1 < H) ? 1.f : 0.f;
        float ax0 = (1.f - wx) * vx0, ax1 = wx * vx1;
        float ay0 = (1.f - wy) * vy0, ay1 = wy * vy1;

        float jx = ((fmaf(q0, xs, fmaf(q1, ys, q2)) + 1.f) * W - 1.f) * 0.5f;
        float jy = ((fmaf(q3, xs, fmaf(q4, ys, q5)) + 1.f) * H - 1.f) * 0.5f;
        float bfx = floorf(jx), bfy = floorf(jy);
        float bx = jx - bfx, by = jy - bfy;
        int u0 = (int)bfx, t0 = (int)bfy;
        float mx = (1.f - bx) * ((u0 >= 0 && u0 < W) ? 1.f : 0.f)
                 + bx * ((u0 + 1 >= 0 && u0 + 1 < W) ? 1.f : 0.f);
        float my = (1.f - by) * ((t0 >= 0 && t0 < H) ? 1.f : 0.f)
                 + by * ((t0 + 1 >= 0 && t0 + 1 < H) ? 1.f : 0.f);
        float m = mx * my;

        float w00 = ax0 * ay0 * m, w01 = ax1 * ay0 * m;
        float w10 = ax0 * ay1 * m, w11 = ax1 * ay1 * m;

        int xc0 = min(max(x0, 0), W - 1), xc1 = min(max(x0 + 1, 0), W - 1);
        int yc0 = min(max(y0, 0), H - 1), yc1 = min(max(y0 + 1, 0), H - 1);
        int i00 = yc0 * W + xc0, i01 = yc0 * W + xc1;
        int i10 = yc1 * W + xc0, i11 = yc1 * W + xc1;

#pragma unroll
        for (int pl = 0; pl < 4; pl++) {
            const float* p = sp + pl * HW;
            d0[pl * (size_t)128 * HW + i] =
                w00 * p[i00] + w01 * p[i01] + w10 * p[i10] + w11 * p[i11];
        }
    }
}

// ---------------------------------------------------------------------------
// 32x32 sample, all 8 batches per block. Optionally fuses the mean-pool.
// ---------------------------------------------------------------------------
template <bool POOL>
__global__ void __launch_bounds__(256) sample32_kernel(
    const float* __restrict__ in, float* __restrict__ out,
    const float* __restrict__ geo, const float* __restrict__ box,
    float* __restrict__ pooled) {
    constexpr int H = 32, W = 32, HW = 1024;
    __shared__ float sp[8 * HW];
    __shared__ float red[64];
    const int c = blockIdx.x;
    for (int j = threadIdx.x; j < 8 * HW; j += 256) {
        int b = j >> 10, p = j & 1023;
        sp[j] = in[((size_t)b * 128 + c) * HW + p];
    }
    const float g0 = geo[c * 6 + 0], g1 = geo[c * 6 + 1], g2 = geo[c * 6 + 2];
    const float g3 = geo[c * 6 + 3], g4 = geo[c * 6 + 4], g5 = geo[c * 6 + 5];
    const float q0 = box[c * 6 + 0], q1 = box[c * 6 + 1], q2 = box[c * 6 + 2];
    const float q3 = box[c * 6 + 3], q4 = box[c * 6 + 4], q5 = box[c * 6 + 5];
    __syncthreads();

    float psum[8];
#pragma unroll
    for (int b = 0; b < 8; b++) psum[b] = 0.f;

    for (int i = threadIdx.x; i < HW; i += 256) {
        int h = i >> 5, w = i & 31;
        float xs = (2.f * w + 1.f) * (1.f / W) - 1.f;
        float ys = (2.f * h + 1.f) * (1.f / H) - 1.f;

        float ix = ((fmaf(g0, xs, fmaf(g1, ys, g2)) + 1.f) * W - 1.f) * 0.5f;
        float iy = ((fmaf(g3, xs, fmaf(g4, ys, g5)) + 1.f) * H - 1.f) * 0.5f;
        float fx = floorf(ix), fy = floorf(iy);
        float wx = ix - fx, wy = iy - fy;
        int x0 = (int)fx, y0 = (int)fy;
        float vx0 = (x0 >= 0 && x0 < W) ? 1.f : 0.f;
        float vx1 = (x0 + 1 >= 0 && x0 + 1 < W) ? 1.f : 0.f;
        float vy0 = (y0 >= 0 && y0 < H) ? 1.f : 0.f;
        float vy1 = (y0 + 1 >= 0 && y0 + 1 < H) ? 1.f : 0.f;
        float ax0 = (1.f - wx) * vx0, ax1 = wx * vx1;
        float ay0 = (1.f - wy) * vy0, ay1 = wy * vy1;

        float jx = ((fmaf(q0, xs, fmaf(q1, ys, q2)) + 1.f) * W - 1.f) * 0.5f;
        float jy = ((fmaf(q3, xs, fmaf(q4, ys, q5)) + 1.f) * H - 1.f) * 0.5f;
        float bfx = floorf(jx), bfy = floorf(jy);
        float bx = jx - bfx, by = jy - bfy;
        int u0 = (int)bfx, t0 = (int)bfy;
        float mx = (1.f - bx) * ((u0 >= 0 && u0 < W) ? 1.f : 0.f)
                 + bx * ((u0 + 1 >= 0 && u0 + 1 < W) ? 1.f : 0.f);
        float my = (1.f - by) * ((t0 >= 0 && t0 < H) ? 1.f : 0.f)
                 + by * ((t0 + 1 >= 0 && t0 + 1 < H) ? 1.f : 0.f);
        float m = mx * my;

        float w00 = ax0 * ay0 * m, w01 = ax1 * ay0 * m;
        float w10 = ax0 * ay1 * m, w11 = ax1 * ay1 * m;

        int xc0 = min(max(x0, 0), W - 1), xc1 = min(max(x0 + 1, 0), W - 1);
        int yc0 = min(max(y0, 0), H - 1), yc1 = min(max(y0 + 1, 0), H - 1);
        int i00 = yc0 * W + xc0, i01 = yc0 * W + xc1;
        int i10 = yc1 * W + xc0, i11 = yc1 * W + xc1;

#pragma unroll
        for (int b = 0; b < 8; b++) {
            const float* p = sp + b * HW;
            float s = w00 * p[i00] + w01 * p[i01] + w10 * p[i10] + w11 * p[i11];
            out[((size_t)b * 128 + c) * HW + i] = s;
            if (POOL) psum[b] += s;
        }
    }

    if (POOL) {
        int lane = threadIdx.x & 31, wid = threadIdx.x >> 5;
#pragma unroll
        for (int b = 0; b < 8; b++) {
            float v = psum[b];
            v += __shfl_down_sync(0xffffffff, v, 16);
            v += __shfl_down_sync(0xffffffff, v, 8);
            v += __shfl_down_sync(0xffffffff, v, 4);
            v += __shfl_down_sync(0xffffffff, v, 2);
            v += __shfl_down_sync(0xffffffff, v, 1);
            if (lane == 0) red[wid * 8 + b] = v;
        }
        __syncthreads();
        if (threadIdx.x < 8) {
            float s = 0.f;
#pragma unroll
            for (int w2 = 0; w2 < 8; w2++) s += red[w2 * 8 + threadIdx.x];
            pooled[threadIdx.x * 128 + c] = s * (1.f / 1024.f);
        }
    }
}

// ---------------------------------------------------------------------------
// Big channel-mix GEMM (HW=4096): 64ch x 128px per block, 512 blocks.
// Thread = 4ch x 8px, f32x2 accumulators. sL indexed with LOCAL channel.
// ---------------------------------------------------------------------------
__global__ void __launch_bounds__(256) mixgemm64_kernel(
    const float* __restrict__ L, const float* __restrict__ in,
    float* __restrict__ out) {
    constexpr int HW = 4096, TN = 128, KC = 16;
    __shared__ float sL[KC][64];
    __shared__ float sIn[KC][TN];
    const int b = blockIdx.x >> 6;                       // /64
    const int rem = blockIdx.x & 63;
    const int px0 = (rem >> 1) * TN;
    const int ch0 = (rem & 1) * 64;
    const int tid = threadIdx.x;
    const int p0 = (tid & 15) * 8;
    const int cl = (tid >> 4) * 4;                       // LOCAL channel 0..60

    unsigned long long acc[2][8];
#pragma unroll
    for (int i = 0; i < 2; i++)
#pragma unroll
        for (int j = 0; j < 8; j++) acc[i][j] = 0ULL;

    for (int k0 = 0; k0 < 128; k0 += KC) {
        __syncthreads();
        {   // sL[k][c_local] = L[(ch0+c_local)*128 + k0+k]
            int lc = tid >> 2, kk = (tid & 3) * 4;
            float4 v = *(const float4*)&L[(ch0 + lc) * 128 + k0 + kk];
            sL[kk + 0][lc] = v.x; sL[kk + 1][lc] = v.y;
            sL[kk + 2][lc] = v.z; sL[kk + 3][lc] = v.w;
        }
        {   // sIn: 16k x 128px, 8 floats per thread
            int k = tid >> 4, pp = (tid & 15) * 8;
            const float* src = in + ((size_t)b * 128 + k0 + k) * HW + px0 + pp;
            *(float4*)&sIn[k][pp]     = *(const float4*)src;
            *(float4*)&sIn[k][pp + 4] = *(const float4*)(src + 4);
        }
        __syncthreads();

#pragma unroll
        for (int k = 0; k < KC; k++) {
            ulonglong2 a01 = *(const ulonglong2*)&sL[k][cl];
            float4 bv0 = *(const float4*)&sIn[k][p0];
            float4 bv1 = *(const float4*)&sIn[k][p0 + 4];
            float bp[8] = {bv0.x, bv0.y, bv0.z, bv0.w, bv1.x, bv1.y, bv1.z, bv1.w};
#pragma unroll
            for (int j = 0; j < 8; j++) {
                unsigned long long bb;
                unsigned r = __float_as_uint(bp[j]);
                asm("mov.b64 %0, {%1, %1};" : "=l"(bb) : "r"(r));
                asm("fma.rn.f32x2 %0, %1, %2, %0;" : "+l"(acc[0][j]) : "l"(a01.x), "l"(bb));
                asm("fma.rn.f32x2 %0, %1, %2, %0;" : "+l"(acc[1][j]) : "l"(a01.y), "l"(bb));
            }
        }
    }

#pragma unroll
    for (int cc = 0; cc < 2; cc++) {
        float lo[8], hi[8];
#pragma unroll
        for (int j = 0; j < 8; j++)
            asm("mov.b64 {%0, %1}, %2;" : "=r"(*(unsigned*)&lo[j]),
                "=r"(*(unsigned*)&hi[j]) : "l"(acc[cc][j]));
        float* r0 = out + ((size_t)b * 128 + ch0 + cl + 2 * cc) * HW + px0 + p0;
        float* r1 = r0 + HW;
        *(float4*)r0       = make_float4(lo[0], lo[1], lo[2], lo[3]);
        *(float4*)(r0 + 4) = make_float4(lo[4], lo[5], lo[6], lo[7]);
        *(float4*)r1       = make_float4(hi[0], hi[1], hi[2], hi[3]);
        *(float4*)(r1 + 4) = make_float4(hi[4], hi[5], hi[6], hi[7]);
    }
}

// ---------------------------------------------------------------------------
// Small channel-mix GEMM (HW=1024): 32ch x 64px per block, 512 blocks.
// Thread = 2ch x 4px. sL indexed with LOCAL channel.
// ---------------------------------------------------------------------------
__global__ void __launch_bounds__(256) mixgemm32_kernel(
    const float* __restrict__ L, const float* __restrict__ in,
    float* __restrict__ out) {
    constexpr int HW = 1024, TN = 64, KC = 16;
    __shared__ float sL[KC][32];
    __shared__ float sIn[KC][TN];
    const int b = blockIdx.x >> 6;                       // /64
    const int rem = blockIdx.x & 63;
    const int px0 = (rem >> 2) * TN;
    const int ch0 = (rem & 3) * 32;
    const int tid = threadIdx.x;
    const int p0 = (tid & 15) * 4;
    const int cl = (tid >> 4) * 2;                       // LOCAL channel 0..30

    unsigned long long acc[4];
#pragma unroll
    for (int j = 0; j < 4; j++) acc[j] = 0ULL;

    for (int k0 = 0; k0 < 128; k0 += KC) {
        __syncthreads();
        {   // sL[k][c_local]: 32c x 16k = 512 floats, 2 per thread
            int lc = tid >> 3, kk = (tid & 7) * 2;
            float2 v = *(const float2*)&L[(ch0 + lc) * 128 + k0 + kk];
            sL[kk + 0][lc] = v.x; sL[kk + 1][lc] = v.y;
        }
        {   // sIn: 16k x 64px = 1024 floats, 4 per thread
            int k = tid >> 4, pp = (tid & 15) * 4;
            const float* src = in + ((size_t)b * 128 + k0 + k) * HW + px0 + pp;
            *(float4*)&sIn[k][pp] = *(const float4*)src;
        }
        __syncthreads();

#pragma unroll
        for (int k = 0; k < KC; k++) {
            unsigned long long av = *(const unsigned long long*)&sL[k][cl];
            float4 bv = *(const float4*)&sIn[k][p0];
            float bp[4] = {bv.x, bv.y, bv.z, bv.w};
#pragma unroll
            for (int j = 0; j < 4; j++) {
                unsigned long long bb;
                unsigned r = __float_as_uint(bp[j]);
                asm("mov.b64 %0, {%1, %1};" : "=l"(bb) : "r"(r));
                asm("fma.rn.f32x2 %0, %1, %2, %0;" : "+l"(acc[j]) : "l"(av), "l"(bb));
            }
        }
    }

    float lo[4], hi[4];
#pragma unroll
    for (int j = 0; j < 4; j++)
        asm("mov.b64 {%0, %1}, %2;" : "=r"(*(unsigned*)&lo[j]),
            "=r"(*(unsigned*)&hi[j]) : "l"(acc[j]));
    float* r0 = out + ((size_t)b * 128 + ch0 + cl) * HW + px0 + p0;
    float* r1 = r0 + HW;
    *(float4*)r0 = make_float4(lo[0], lo[1], lo[2], lo[3]);
    *(float4*)r1 = make_float4(hi[0], hi[1], hi[2], hi[3]);
}

// ---------------------------------------------------------------------------
// MaxPool2d_G k=2, 64x64. 4 planes per block (R4 version).
// ---------------------------------------------------------------------------
__global__ void __launch_bounds__(256) maxpool_kernel(const float* __restrict__ in,
                                                      float* __restrict__ out) {
    extern __shared__ float A[];               // 4 * 4160
    __shared__ float rb[8];
    __shared__ int   ib[8];
    __shared__ int   argm[4];
    const int tid = threadIdx.x;
    const int pl = tid >> 6;
    const int t = tid & 63;
    const int base = blockIdx.x * 4;
    float* Ap = A + pl * 4160;
    const float* src = in + (size_t)(base + pl) * 4096;

    {
        float run = 0.f;
#pragma unroll 8
        for (int y = 0; y < 64; y++) {
            run += __ldg(&src[y * 64 + t]);
            Ap[y * 65 + t] = run;
        }
    }
    __syncthreads();
    {
        float run = 0.f;
        float* row = Ap + t * 65;
#pragma unroll 8
        for (int x = 0; x < 64; x++) {
            run += row[x];
            row[x] = run;
        }
    }
    __syncthreads();
    {
        const int oy = t;
        const float* rowHi = Ap + min(oy + 15, 63) * 65;
        const float* rowLo = Ap + (oy - 17) * 65;
        const bool hasLo = (oy >= 17);
        float bv = -3.4e38f; int bi = 0;
#pragma unroll 8
        for (int ox = 0; ox < 64; ox++) {
            int x2 = min(ox + 15, 63);
            float s = rowHi[x2];
            if (ox >= 17) s -= rowHi[ox - 17];
            if (hasLo) {
                s -= rowLo[x2];
                if (ox >= 17) s += rowLo[ox - 17];
            }
            if (s > bv) { bv = s; bi = oy * 64 + ox; }
        }
        int lane = tid & 31;
#pragma unroll
        for (int off = 16; off > 0; off >>= 1) {
            float ov = __shfl_down_sync(0xffffffffu, bv, off);
            int oi = __shfl_down_sync(0xffffffffu, bi, off);
            if (ov > bv || (ov == bv && oi < bi)) { bv = ov; bi = oi; }
        }
        if (lane == 0) { rb[tid >> 5] = bv; ib[tid >> 5] = bi; }
    }
    __syncthreads();
    if (t == 0) {
        float v0 = rb[pl * 2], v1 = rb[pl * 2 + 1];
        int i0 = ib[pl * 2], i1 = ib[pl * 2 + 1];
        argm[pl] = (v1 > v0 || (v1 == v0 && i1 < i0)) ? i1 : i0;
    }
    __syncthreads();
    for (int j = tid; j < 4096; j += 256) {
        int p2 = j >> 10, i = j & 1023;
        int am = argm[p2];
        int r0 = am >> 6, c0 = am & 63;
        int ii = i >> 5, jj = i & 31;
        int y = r0 - 16 + ii, x = c0 - 16 + jj;
        float v = 0.f;
        if (y >= 0 && y < 64 && x >= 0 && x < 64)
            v = __ldg(&in[(size_t)(base + p2) * 4096 + y * 64 + x]);
        out[(size_t)(base + p2) * 1024 + i] = v;
    }
}

// ---------------------------------------------------------------------------
// Dense head
// ---------------------------------------------------------------------------
__global__ void dense_kernel(const float* __restrict__ pooled,
                             const float* __restrict__ w,
                             const float* __restrict__ bias,
                             float* __restrict__ out) {
    int t = threadIdx.x;
    if (t < 80) {
        int b = t / 10, o = t % 10;
        float a = bias[o];
        for (int c = 0; c < 128; c++) a = fmaf(pooled[b * 128 + c], w[o * 128 + c], a);
        out[b * 10 + o] = a;
    }
}

extern "C" void kernel_launch(void* const* d_in, const int* in_sizes, int n_in,
                              void* d_out, int out_size) {
    const float* x     = (const float*)d_in[0];
    const float* geo0  = (const float*)d_in[1];
    const float* lin0  = (const float*)d_in[2];
    const float* box0  = (const float*)d_in[3];
    const float* geos  = (const float*)d_in[4];
    const float* lins  = (const float*)d_in[5];
    const float* boxes = (const float*)d_in[6];
    const float* dw    = (const float*)d_in[7];
    const float* db    = (const float*)d_in[8];
    float* out  = (float*)d_out;
    float* feat = out + 80;

    float *y64, *h64, *a32, *b32, *pool;
    cudaGetSymbolAddress((void**)&y64, g_y64);
    cudaGetSymbolAddress((void**)&h64, g_h64);
    cudaGetSymbolAddress((void**)&a32, g_a32);
    cudaGetSymbolAddress((void**)&b32, g_b32);
    cudaGetSymbolAddress((void**)&pool, g_pool);

    const int smem64 = 4 * 4096 * sizeof(float);    // 64 KB
    const int smemMP = 4 * 4160 * sizeof(float);    // 66.5 KB
    cudaFuncSetAttribute(sample64_kernel<true>,
                         cudaFuncAttributeMaxDynamicSharedMemorySize, smem64);
    cudaFuncSetAttribute(sample64_kernel<false>,
                         cudaFuncAttributeMaxDynamicSharedMemorySize, smem64);
    cudaFuncSetAttribute(maxpool_kernel,
                         cudaFuncAttributeMaxDynamicSharedMemorySize, smemMP);

    // inLay: fused mix3 + sample (64x64)
    sample64_kernel<true><<<256, 256, smem64>>>(x, lin0, h64, geo0, box0);
    // layer 0 (64x64)
    mixgemm64_kernel<<<512, 256>>>(lins + 0 * 16384, h64, y64);
    sample64_kernel<false><<<256, 256, smem64>>>(y64, nullptr, h64,
                                                 geos + 0 * 768, boxes + 0 * 768);
    // layer 1: maxpool_g
    maxpool_kernel<<<256, 256, smemMP>>>(h64, a32);
    // layer 2 (32x32)
    mixgemm32_kernel<<<512, 256>>>(lins + 1 * 16384, a32, b32);
    sample32_kernel<false><<<128, 256>>>(b32, a32, geos + 1 * 768, boxes + 1 * 768, nullptr);
    // layer 3 (32x32) -> feat (+ fused mean pool)
    mixgemm32_kernel<<<512, 256>>>(lins + 2 * 16384, a32, b32);
    sample32_kernel<true><<<128, 256>>>(b32, feat, geos + 2 * 768, boxes + 2 * 768, pool);
    // head
    dense_kernel<<<1, 128>>>(pool, dw, db, out);
}

// round 8
// speedup vs baseline: 1.1778x; 1.1778x over previous
#include <cuda_runtime.h>
#include <cuda_bf16.h>

#define BATCH 8
#define CHAN 128

__device__ float g_y64[BATCH * CHAN * 4096];   // 16 MB
__device__ float g_h64[BATCH * CHAN * 4096];   // 16 MB
__device__ float g_a32[BATCH * CHAN * 1024];   // 4 MB
__device__ float g_b32[BATCH * CHAN * 1024];   // 4 MB
__device__ float g_pool[BATCH * CHAN];

// ---------------------------------------------------------------------------
// 64x64 grid_sample * box mask, 4 batches per block (dynamic smem 64KB).
// ---------------------------------------------------------------------------
template <bool FUSE3>
__global__ void __launch_bounds__(256) sample64_kernel(
    const float* __restrict__ in, const float* __restrict__ lin,
    float* __restrict__ out,
    const float* __restrict__ geo, const float* __restrict__ box) {
    constexpr int H = 64, W = 64, HW = 4096;
    extern __shared__ float sp[];              // 4 * HW
    const int c  = blockIdx.x >> 1;
    const int b0 = (blockIdx.x & 1) * 4;

    if (FUSE3) {
        const float l0 = lin[c * 3 + 0], l1 = lin[c * 3 + 1], l2 = lin[c * 3 + 2];
        for (int j = threadIdx.x; j < 4 * HW; j += 256) {
            int pl = j >> 12, p = j & 4095;
            const float* xb = in + (size_t)(b0 + pl) * 3 * HW + p;
            sp[j] = fmaf(l0, xb[0], fmaf(l1, xb[HW], l2 * xb[2 * HW]));
        }
    } else {
        for (int j = threadIdx.x; j < 4 * HW; j += 256) {
            int pl = j >> 12, p = j & 4095;
            sp[j] = in[((size_t)(b0 + pl) * 128 + c) * HW + p];
        }
    }

    const float g0 = geo[c * 6 + 0], g1 = geo[c * 6 + 1], g2 = geo[c * 6 + 2];
    const float g3 = geo[c * 6 + 3], g4 = geo[c * 6 + 4], g5 = geo[c * 6 + 5];
    const float q0 = box[c * 6 + 0], q1 = box[c * 6 + 1], q2 = box[c * 6 + 2];
    const float q3 = box[c * 6 + 3], q4 = box[c * 6 + 4], q5 = box[c * 6 + 5];
    __syncthreads();

    float* d0 = out + ((size_t)b0 * 128 + c) * HW;

    for (int i = threadIdx.x; i < HW; i += 256) {
        int h = i >> 6, w = i & 63;
        float xs = (2.f * w + 1.f) * (1.f / W) - 1.f;
        float ys = (2.f * h + 1.f) * (1.f / H) - 1.f;

        float ix = ((fmaf(g0, xs, fmaf(g1, ys, g2)) + 1.f) * W - 1.f) * 0.5f;
        float iy = ((fmaf(g3, xs, fmaf(g4, ys, g5)) + 1.f) * H - 1.f) * 0.5f;
        float fx = floorf(ix), fy = floorf(iy);
        float wx = ix - fx, wy = iy - fy;
        int x0 = (int)fx, y0 = (int)fy;
        float vx0 = (x0 >= 0 && x0 < W) ? 1.f : 0.f;
        float vx1 = (x0 + 1 >= 0 && x0 + 1 < W) ? 1.f : 0.f;
        float vy0 = (y0 >= 0 && y0 < H) ? 1.f : 0.f;
        float vy1 = (y0 + 1 >= 0 && y0 + 1 < H) ? 1.f : 0.f;
        float ax0 = (1.f - wx) * vx0, ax1 = wx * vx1;
        float ay0 = (1.f - wy) * vy0, ay1 = wy * vy1;

        float jx = ((fmaf(q0, xs, fmaf(q1, ys, q2)) + 1.f) * W - 1.f) * 0.5f;
        float jy = ((fmaf(q3, xs, fmaf(q4, ys, q5)) + 1.f) * H - 1.f) * 0.5f;
        float bfx = floorf(jx), bfy = floorf(jy);
        float bx = jx - bfx, by = jy - bfy;
        int u0 = (int)bfx, t0 = (int)bfy;
        float mx = (1.f - bx) * ((u0 >= 0 && u0 < W) ? 1.f : 0.f)
                 + bx * ((u0 + 1 >= 0 && u0 + 1 < W) ? 1.f : 0.f);
        float my = (1.f - by) * ((t0 >= 0 && t0 < H) ? 1.f : 0.f)
                 + by * ((t0 + 1 >= 0 && t0 + 1 < H) ? 1.f : 0.f);
        float m = mx * my;

        float w00 = ax0 * ay0 * m, w01 = ax1 * ay0 * m;
        float w10 = ax0 * ay1 * m, w11 = ax1 * ay1 * m;

        int xc0 = min(max(x0, 0), W - 1), xc1 = min(max(x0 + 1, 0), W - 1);
        int yc0 = min(max(y0, 0), H - 1), yc1 = min(max(y0 + 1, 0), H - 1);
        int i00 = yc0 * W + xc0, i01 = yc0 * W + xc1;
        int i10 = yc1 * W + xc0, i11 = yc1 * W + xc1;

#pragma unroll
        for (int pl = 0; pl < 4; pl++) {
            const float* p = sp + pl * HW;
            d0[pl * (size_t)128 * HW + i] =
                w00 * p[i00] + w01 * p[i01] + w10 * p[i10] + w11 * p[i11];
        }
    }
}

// ---------------------------------------------------------------------------
// 32x32 sample, all 8 batches per block. Optionally fuses the mean-pool.
// ---------------------------------------------------------------------------
template <bool POOL>
__global__ void __launch_bounds__(256) sample32_kernel(
    const float* __restrict__ in, float* __restrict__ out,
    const float* __restrict__ geo, const float* __restrict__ box,
    float* __restrict__ pooled) {
    constexpr int H = 32, W = 32, HW = 1024;
    __shared__ float sp[8 * HW];
    __shared__ float red[64];
    const int c = blockIdx.x;
    for (int j = threadIdx.x; j < 8 * HW; j += 256) {
        int b = j >> 10, p = j & 1023;
        sp[j] = in[((size_t)b * 128 + c) * HW + p];
    }
    const float g0 = geo[c * 6 + 0], g1 = geo[c * 6 + 1], g2 = geo[c * 6 + 2];
    const float g3 = geo[c * 6 + 3], g4 = geo[c * 6 + 4], g5 = geo[c * 6 + 5];
    const float q0 = box[c * 6 + 0], q1 = box[c * 6 + 1], q2 = box[c * 6 + 2];
    const float q3 = box[c * 6 + 3], q4 = box[c * 6 + 4], q5 = box[c * 6 + 5];
    __syncthreads();

    float psum[8];
#pragma unroll
    for (int b = 0; b < 8; b++) psum[b] = 0.f;

    for (int i = threadIdx.x; i < HW; i += 256) {
        int h = i >> 5, w = i & 31;
        float xs = (2.f * w + 1.f) * (1.f / W) - 1.f;
        float ys = (2.f * h + 1.f) * (1.f / H) - 1.f;

        float ix = ((fmaf(g0, xs, fmaf(g1, ys, g2)) + 1.f) * W - 1.f) * 0.5f;
        float iy = ((fmaf(g3, xs, fmaf(g4, ys, g5)) + 1.f) * H - 1.f) * 0.5f;
        float fx = floorf(ix), fy = floorf(iy);
        float wx = ix - fx, wy = iy - fy;
        int x0 = (int)fx, y0 = (int)fy;
        float vx0 = (x0 >= 0 && x0 < W) ? 1.f : 0.f;
        float vx1 = (x0 + 1 >= 0 && x0 + 1 < W) ? 1.f : 0.f;
        float vy0 = (y0 >= 0 && y0 < H) ? 1.f : 0.f;
        float vy1 = (y0 + 1 >= 0 && y0 + 1 < H) ? 1.f : 0.f;
        float ax0 = (1.f - wx) * vx0, ax1 = wx * vx1;
        float ay0 = (1.f - wy) * vy0, ay1 = wy * vy1;

        float jx = ((fmaf(q0, xs, fmaf(q1, ys, q2)) + 1.f) * W - 1.f) * 0.5f;
        float jy = ((fmaf(q3, xs, fmaf(q4, ys, q5)) + 1.f) * H - 1.f) * 0.5f;
        float bfx = floorf(jx), bfy = floorf(jy);
        float bx = jx - bfx, by = jy - bfy;
        int u0 = (int)bfx, t0 = (int)bfy;
        float mx = (1.f - bx) * ((u0 >= 0 && u0 < W) ? 1.f : 0.f)
                 + bx * ((u0 + 1 >= 0 && u0 + 1 < W) ? 1.f : 0.f);
        float my = (1.f - by) * ((t0 >= 0 && t0 < H) ? 1.f : 0.f)
                 + by * ((t0 + 1 >= 0 && t0 + 1 < H) ? 1.f : 0.f);
        float m = mx * my;

        float w00 = ax0 * ay0 * m, w01 = ax1 * ay0 * m;
        float w10 = ax0 * ay1 * m, w11 = ax1 * ay1 * m;

        int xc0 = min(max(x0, 0), W - 1), xc1 = min(max(x0 + 1, 0), W - 1);
        int yc0 = min(max(y0, 0), H - 1), yc1 = min(max(y0 + 1, 0), H - 1);
        int i00 = yc0 * W + xc0, i01 = yc0 * W + xc1;
        int i10 = yc1 * W + xc0, i11 = yc1 * W + xc1;

#pragma unroll
        for (int b = 0; b < 8; b++) {
            const float* p = sp + b * HW;
            float s = w00 * p[i00] + w01 * p[i01] + w10 * p[i10] + w11 * p[i11];
            out[((size_t)b * 128 + c) * HW + i] = s;
            if (POOL) psum[b] += s;
        }
    }

    if (POOL) {
        int lane = threadIdx.x & 31, wid = threadIdx.x >> 5;
#pragma unroll
        for (int b = 0; b < 8; b++) {
            float v = psum[b];
            v += __shfl_down_sync(0xffffffff, v, 16);
            v += __shfl_down_sync(0xffffffff, v, 8);
            v += __shfl_down_sync(0xffffffff, v, 4);
            v += __shfl_down_sync(0xffffffff, v, 2);
            v += __shfl_down_sync(0xffffffff, v, 1);
            if (lane == 0) red[wid * 8 + b] = v;
        }
        __syncthreads();
        if (threadIdx.x < 8) {
            float s = 0.f;
#pragma unroll
            for (int w2 = 0; w2 < 8; w2++) s += red[w2 * 8 + threadIdx.x];
            pooled[threadIdx.x * 128 + c] = s * (1.f / 1024.f);
        }
    }
}

// ---------------------------------------------------------------------------
// Big channel-mix GEMM (R4 version): 128ch x 128px per block, grid 256.
// Thread = 8ch x 8px, f32x2 accumulators.
// ---------------------------------------------------------------------------
__global__ void __launch_bounds__(256, 2) mixgemm_big_kernel(
    const float* __restrict__ L, const float* __restrict__ in,
    float* __restrict__ out) {
    constexpr int HW = 4096, TN = 128, KC = 16, CPT = 8;
    __shared__ float sL[KC][128];
    __shared__ float sIn[KC][TN];
    constexpr int NGROUP = TN / 8;
    const int tiles = HW / TN;
    const int b = blockIdx.x / tiles;
    const int px0 = (blockIdx.x % tiles) * TN;
    const int tid = threadIdx.x;
    const int tn = tid % NGROUP;
    const int tm = tid / NGROUP;
    const int c0 = tm * CPT;
    const int p0 = tn * 8;

    unsigned long long acc[CPT / 2][8];
#pragma unroll
    for (int i = 0; i < CPT / 2; i++)
#pragma unroll
        for (int j = 0; j < 8; j++) acc[i][j] = 0ULL;

    for (int k0 = 0; k0 < 128; k0 += KC) {
        __syncthreads();
        {
            int lc = tid >> 1, kk = (tid & 1) * 8;
            float4 v0 = *(const float4*)&L[lc * 128 + k0 + kk];
            float4 v1 = *(const float4*)&L[lc * 128 + k0 + kk + 4];
            sL[kk + 0][lc] = v0.x; sL[kk + 1][lc] = v0.y;
            sL[kk + 2][lc] = v0.z; sL[kk + 3][lc] = v0.w;
            sL[kk + 4][lc] = v1.x; sL[kk + 5][lc] = v1.y;
            sL[kk + 6][lc] = v1.z; sL[kk + 7][lc] = v1.w;
        }
        {
            int k = tid >> 4, pp = (tid & 15) * 8;
            const float* src = in + ((size_t)b * 128 + k0 + k) * HW + px0 + pp;
            *(float4*)&sIn[k][pp]     = *(const float4*)src;
            *(float4*)&sIn[k][pp + 4] = *(const float4*)(src + 4);
        }
        __syncthreads();

#pragma unroll
        for (int k = 0; k < KC; k++) {
            unsigned long long av[CPT / 2];
            {
                ulonglong2 a01 = *(const ulonglong2*)&sL[k][c0];
                av[0] = a01.x; av[1] = a01.y;
                ulonglong2 a23 = *(const ulonglong2*)&sL[k][c0 + 4];
                av[2] = a23.x; av[3] = a23.y;
            }
            float4 bv0 = *(const float4*)&sIn[k][p0];
            float4 bv1 = *(const float4*)&sIn[k][p0 + 4];
            float bp[8] = {bv0.x, bv0.y, bv0.z, bv0.w, bv1.x, bv1.y, bv1.z, bv1.w};
            unsigned long long bb[8];
#pragma unroll
            for (int j = 0; j < 8; j++) {
                unsigned r = __float_as_uint(bp[j]);
                asm("mov.b64 %0, {%1, %1};" : "=l"(bb[j]) : "r"(r));
            }
#pragma unroll
            for (int cc = 0; cc < CPT / 2; cc++)
#pragma unroll
                for (int j = 0; j < 8; j++)
                    asm("fma.rn.f32x2 %0, %1, %2, %0;"
                        : "+l"(acc[cc][j]) : "l"(av[cc]), "l"(bb[j]));
        }
    }

#pragma unroll
    for (int cc = 0; cc < CPT / 2; cc++) {
        float lo[8], hi[8];
#pragma unroll
        for (int j = 0; j < 8; j++)
            asm("mov.b64 {%0, %1}, %2;" : "=r"(*(unsigned*)&lo[j]),
                "=r"(*(unsigned*)&hi[j]) : "l"(acc[cc][j]));
        float* r0 = out + ((size_t)b * 128 + c0 + 2 * cc) * HW + px0 + p0;
        float* r1 = r0 + HW;
        *(float4*)r0       = make_float4(lo[0], lo[1], lo[2], lo[3]);
        *(float4*)(r0 + 4) = make_float4(lo[4], lo[5], lo[6], lo[7]);
        *(float4*)r1       = make_float4(hi[0], hi[1], hi[2], hi[3]);
        *(float4*)(r1 + 4) = make_float4(hi[4], hi[5], hi[6], hi[7]);
    }
}

// ---------------------------------------------------------------------------
// Small channel-mix GEMM (HW=1024): 64ch x 64px per block, 128 threads,
// grid 256 (8b x 16 px-tiles x 2 channel halves). Same intensity as R4
// (thread = 4ch x 8px), but 2x the blocks and 2+ blocks/SM.
// ---------------------------------------------------------------------------
__global__ void __launch_bounds__(128) mixgemm32h_kernel(
    const float* __restrict__ L, const float* __restrict__ in,
    float* __restrict__ out) {
    constexpr int HW = 1024, TN = 64, KC = 16;
    __shared__ float sL[KC][64];
    __shared__ float sIn[KC][TN];
    const int b = blockIdx.x >> 5;
    const int rem = blockIdx.x & 31;
    const int px0 = (rem >> 1) * TN;
    const int ch0 = (rem & 1) * 64;
    const int tid = threadIdx.x;
    const int tn = tid & 7;          // pixel group 0..7
    const int tm = tid >> 3;         // channel group 0..15
    const int cl = tm * 4;           // LOCAL channel
    const int p0 = tn * 8;

    unsigned long long acc[2][8];
#pragma unroll
    for (int i = 0; i < 2; i++)
#pragma unroll
        for (int j = 0; j < 8; j++) acc[i][j] = 0ULL;

    for (int k0 = 0; k0 < 128; k0 += KC) {
        __syncthreads();
        {   // sL[k][c_local]: 64c x 16k = 1024 floats, 8 per thread
            int lc = tid >> 1, kk = (tid & 1) * 8;
            float4 v0 = *(const float4*)&L[(ch0 + lc) * 128 + k0 + kk];
            float4 v1 = *(const float4*)&L[(ch0 + lc) * 128 + k0 + kk + 4];
            sL[kk + 0][lc] = v0.x; sL[kk + 1][lc] = v0.y;
            sL[kk + 2][lc] = v0.z; sL[kk + 3][lc] = v0.w;
            sL[kk + 4][lc] = v1.x; sL[kk + 5][lc] = v1.y;
            sL[kk + 6][lc] = v1.z; sL[kk + 7][lc] = v1.w;
        }
        {   // sIn: 16k x 64px = 1024 floats, 8 per thread
            int k = tid >> 3, pp = (tid & 7) * 8;
            const float* src = in + ((size_t)b * 128 + k0 + k) * HW + px0 + pp;
            *(float4*)&sIn[k][pp]     = *(const float4*)src;
            *(float4*)&sIn[k][pp + 4] = *(const float4*)(src + 4);
        }
        __syncthreads();

#pragma unroll
        for (int k = 0; k < KC; k++) {
            ulonglong2 a01 = *(const ulonglong2*)&sL[k][cl];
            float4 bv0 = *(const float4*)&sIn[k][p0];
            float4 bv1 = *(const float4*)&sIn[k][p0 + 4];
            float bp[8] = {bv0.x, bv0.y, bv0.z, bv0.w, bv1.x, bv1.y, bv1.z, bv1.w};
#pragma unroll
            for (int j = 0; j < 8; j++) {
                unsigned long long bb;
                unsigned r = __float_as_uint(bp[j]);
                asm("mov.b64 %0, {%1, %1};" : "=l"(bb) : "r"(r));
                asm("fma.rn.f32x2 %0, %1, %2, %0;" : "+l"(acc[0][j]) : "l"(a01.x), "l"(bb));
                asm("fma.rn.f32x2 %0, %1, %2, %0;" : "+l"(acc[1][j]) : "l"(a01.y), "l"(bb));
            }
        }
    }

#pragma unroll
    for (int cc = 0; cc < 2; cc++) {
        float lo[8], hi[8];
#pragma unroll
        for (int j = 0; j < 8; j++)
            asm("mov.b64 {%0, %1}, %2;" : "=r"(*(unsigned*)&lo[j]),
                "=r"(*(unsigned*)&hi[j]) : "l"(acc[cc][j]));
        float* r0 = out + ((size_t)b * 128 + ch0 + cl + 2 * cc) * HW + px0 + p0;
        float* r1 = r0 + HW;
        *(float4*)r0       = make_float4(lo[0], lo[1], lo[2], lo[3]);
        *(float4*)(r0 + 4) = make_float4(lo[4], lo[5], lo[6], lo[7]);
        *(float4*)r1       = make_float4(hi[0], hi[1], hi[2], hi[3]);
        *(float4*)(r1 + 4) = make_float4(hi[4], hi[5], hi[6], hi[7]);
    }
}

// ---------------------------------------------------------------------------
// MaxPool2d_G k=2, 64x64. 2 planes per block, grid 512, smem 33KB.
// Prefix phases split into 2 segments + parallel fix-up (serial 64 -> 32).
// ---------------------------------------------------------------------------
__global__ void __launch_bounds__(256) maxpool_kernel(const float* __restrict__ in,
                                                      float* __restrict__ out) {
    extern __shared__ float A[];               // 2 * 4160 floats
    __shared__ float rb[8];
    __shared__ int   ib[8];
    __shared__ int   argm[2];
    const int tid = threadIdx.x;
    const int pl = tid >> 7;                   // 0..1
    const int t = tid & 127;
    const int base = blockIdx.x * 2;
    float* Ap = A + pl * 4160;
    const float* src = in + (size_t)(base + pl) * 4096;

    // phase 1: column prefix, 2 y-segments of 32
    {
        int col = t & 63, y0 = (t >> 6) * 32;
        float run = 0.f;
#pragma unroll 8
        for (int y = y0; y < y0 + 32; y++) {
            run += __ldg(&src[y * 64 + col]);
            Ap[y * 65 + col] = run;
        }
    }
    __syncthreads();
    // fix-up: add lower-segment total (row 31) to upper rows
    for (int j = t; j < 2048; j += 128) {
        int col = j & 63, y = 32 + (j >> 6);
        Ap[y * 65 + col] += Ap[31 * 65 + col];
    }
    __syncthreads();
    // phase 2: row prefix, 2 x-segments of 32
    {
        int row = t & 63, x0 = (t >> 6) * 32;
        float run = 0.f;
        float* r = Ap + row * 65;
#pragma unroll 8
        for (int x = x0; x < x0 + 32; x++) { run += r[x]; r[x] = run; }
    }
    __syncthreads();
    // fix-up: add left-segment total (col 31) to right cols
    for (int j = t; j < 2048; j += 128) {
        int row = j >> 5, x = 32 + (j & 31);
        Ap[row * 65 + x] += Ap[row * 65 + 31];
    }
    __syncthreads();
    // phase 3: windowed box-sum via 4-tap SAT + argmax (first-index ties)
    {
        float bv = -3.4e38f; int bi = 0;
        for (int j = t; j < 4096; j += 128) {
            int oy = j >> 6, ox = j & 63;
            int y1 = max(oy - 16, 0), y2 = min(oy + 15, 63);
            int x1 = max(ox - 16, 0), x2 = min(ox + 15, 63);
            float s = Ap[y2 * 65 + x2];
            if (x1 > 0) s -= Ap[y2 * 65 + x1 - 1];
            if (y1 > 0) s -= Ap[(y1 - 1) * 65 + x2];
            if (x1 > 0 && y1 > 0) s += Ap[(y1 - 1) * 65 + x1 - 1];
            if (s > bv) { bv = s; bi = j; }
        }
        int lane = tid & 31;
#pragma unroll
        for (int off = 16; off > 0; off >>= 1) {
            float ov = __shfl_down_sync(0xffffffffu, bv, off);
            int oi = __shfl_down_sync(0xffffffffu, bi, off);
            if (ov > bv || (ov == bv && oi < bi)) { bv = ov; bi = oi; }
        }
        if (lane == 0) { rb[tid >> 5] = bv; ib[tid >> 5] = bi; }
    }
    __syncthreads();
    if (t == 0) {
        float bv = rb[pl * 4]; int bi = ib[pl * 4];
#pragma unroll
        for (int w2 = 1; w2 < 4; w2++) {
            float ov = rb[pl * 4 + w2]; int oi = ib[pl * 4 + w2];
            if (ov > bv || (ov == bv && oi < bi)) { bv = ov; bi = oi; }
        }
        argm[pl] = bi;
    }
    __syncthreads();
    // phase 4: gather 32x32 window around argmax (zero pad), from gmem
    for (int j = tid; j < 2048; j += 256) {
        int p2 = j >> 10, i = j & 1023;
        int am = argm[p2];
        int r0 = am >> 6, c0 = am & 63;
        int ii = i >> 5, jj = i & 31;
        int y = r0 - 16 + ii, x = c0 - 16 + jj;
        float v = 0.f;
        if (y >= 0 && y < 64 && x >= 0 && x < 64)
            v = __ldg(&in[(size_t)(base + p2) * 4096 + y * 64 + x]);
        out[(size_t)(base + p2) * 1024 + i] = v;
    }
}

// ---------------------------------------------------------------------------
// Dense head
// ---------------------------------------------------------------------------
__global__ void dense_kernel(const float* __restrict__ pooled,
                             const float* __restrict__ w,
                             const float* __restrict__ bias,
                             float* __restrict__ out) {
    int t = threadIdx.x;
    if (t < 80) {
        int b = t / 10, o = t % 10;
        float a = bias[o];
        for (int c = 0; c < 128; c++) a = fmaf(pooled[b * 128 + c], w[o * 128 + c], a);
        out[b * 10 + o] = a;
    }
}

extern "C" void kernel_launch(void* const* d_in, const int* in_sizes, int n_in,
                              void* d_out, int out_size) {
    const float* x     = (const float*)d_in[0];
    const float* geo0  = (const float*)d_in[1];
    const float* lin0  = (const float*)d_in[2];
    const float* box0  = (const float*)d_in[3];
    const float* geos  = (const float*)d_in[4];
    const float* lins  = (const float*)d_in[5];
    const float* boxes = (const float*)d_in[6];
    const float* dw    = (const float*)d_in[7];
    const float* db    = (const float*)d_in[8];
    float* out  = (float*)d_out;
    float* feat = out + 80;

    float *y64, *h64, *a32, *b32, *pool;
    cudaGetSymbolAddress((void**)&y64, g_y64);
    cudaGetSymbolAddress((void**)&h64, g_h64);
    cudaGetSymbolAddress((void**)&a32, g_a32);
    cudaGetSymbolAddress((void**)&b32, g_b32);
    cudaGetSymbolAddress((void**)&pool, g_pool);

    const int smem64 = 4 * 4096 * sizeof(float);    // 64 KB
    const int smemMP = 2 * 4160 * sizeof(float);    // 33.3 KB
    cudaFuncSetAttribute(sample64_kernel<true>,
                         cudaFuncAttributeMaxDynamicSharedMemorySize, smem64);
    cudaFuncSetAttribute(sample64_kernel<false>,
                         cudaFuncAttributeMaxDynamicSharedMemorySize, smem64);
    cudaFuncSetAttribute(maxpool_kernel,
                         cudaFuncAttributeMaxDynamicSharedMemorySize, smemMP);

    // inLay: fused mix3 + sample (64x64)
    sample64_kernel<true><<<256, 256, smem64>>>(x, lin0, h64, geo0, box0);
    // layer 0 (64x64)
    mixgemm_big_kernel<<<256, 256>>>(lins + 0 * 16384, h64, y64);
    sample64_kernel<false><<<256, 256, smem64>>>(y64, nullptr, h64,
                                                 geos + 0 * 768, boxes + 0 * 768);
    // layer 1: maxpool_g (2 planes/block, split prefix)
    maxpool_kernel<<<512, 256, smemMP>>>(h64, a32);
    // layer 2 (32x32)
    mixgemm32h_kernel<<<256, 128>>>(lins + 1 * 16384, a32, b32);
    sample32_kernel<false><<<128, 256>>>(b32, a32, geos + 1 * 768, boxes + 1 * 768, nullptr);
    // layer 3 (32x32) -> feat (+ fused mean pool)
    mixgemm32h_kernel<<<256, 128>>>(lins + 2 * 16384, a32, b32);
    sample32_kernel<true><<<128, 256>>>(b32, feat, geos + 2 * 768, boxes + 2 * 768, pool);
    // head
    dense_kernel<<<1, 128>>>(pool, dw, db, out);
}